// round 16
// baseline (speedup 1.0000x reference)
#include <cuda_runtime.h>

#define NB 256
#define NP 20000

__device__ float g_M[NB * 45];

__device__ __host__ __forceinline__ constexpr int tidx(int i, int j) {
    return 9 * i - i * (i - 1) / 2 + (j - i);
}

// ---------------------------------------------------------------------------
// Kernel 1: per-batch weighted Gram matrix. Depth-2 software pipeline (two
// quads / 16 loads in flight). Per-thread accumulation sequence (quads at
// i, i+1024, ..., i+18432, then singles stride 256) is IDENTICAL to the
// round-11/14 passing kernels -> M bitwise identical.
// ---------------------------------------------------------------------------
__device__ __forceinline__ void accum_point(float4 p, float wt, float* __restrict__ s) {
    float v[9];
    v[0] = p.z * p.x; v[1] = p.z * p.y; v[2] = p.z;
    v[3] = p.w * p.x; v[4] = p.w * p.y; v[5] = p.w;
    v[6] = p.x;       v[7] = p.y;       v[8] = 1.f;
    float wv[9];
#pragma unroll
    for (int k = 0; k < 9; k++) wv[k] = wt * v[k];
    int idx = 0;
#pragma unroll
    for (int i2 = 0; i2 < 9; i2++) {
#pragma unroll
        for (int j = i2; j < 9; j++) {
            s[idx] = fmaf(v[i2], wv[j], s[idx]);
            idx++;
        }
    }
}

__global__ void __launch_bounds__(256) xtx_kernel(const float4* __restrict__ x,
                                                  const float* __restrict__ w) {
    int b = blockIdx.x;
    const float4* xb = x + (size_t)b * NP;
    const float*  wb = w + (size_t)b * NP;

    float s[45];
#pragma unroll
    for (int k = 0; k < 45; k++) s[k] = 0.f;

    // NP=20000, 256 threads: every thread has >= 19 full quads, so the two
    // priming quads below are always in-bounds (a+1792 <= 2047 < NP).
    int a = threadIdx.x;
    float4 p0 = xb[a];
    float  w0 = wb[a];
    float4 p1 = xb[a + 256];
    float  w1 = wb[a + 256];
    float4 p2 = xb[a + 512];
    float  w2 = wb[a + 512];
    float4 p3 = xb[a + 768];
    float  w3 = wb[a + 768];

    int bpos = a + 1024;
    float4 q0 = xb[bpos];
    float  v0 = wb[bpos];
    float4 q1 = xb[bpos + 256];
    float  v1 = wb[bpos + 256];
    float4 q2 = xb[bpos + 512];
    float  v2 = wb[bpos + 512];
    float4 q3 = xb[bpos + 768];
    float  v3 = wb[bpos + 768];

    int cpos = bpos + 1024;
    while (cpos + 768 < NP) {
        float4 r0 = xb[cpos];
        float  u0 = wb[cpos];
        float4 r1 = xb[cpos + 256];
        float  u1 = wb[cpos + 256];
        float4 r2 = xb[cpos + 512];
        float  u2 = wb[cpos + 512];
        float4 r3 = xb[cpos + 768];
        float  u3 = wb[cpos + 768];

        accum_point(p0, w0, s);
        accum_point(p1, w1, s);
        accum_point(p2, w2, s);
        accum_point(p3, w3, s);

        p0 = q0; w0 = v0;
        p1 = q1; w1 = v1;
        p2 = q2; w2 = v2;
        p3 = q3; w3 = v3;
        q0 = r0; v0 = u0;
        q1 = r1; v1 = u1;
        q2 = r2; v2 = u2;
        q3 = r3; v3 = u3;
        bpos = cpos;
        cpos += 1024;
    }
    accum_point(p0, w0, s);
    accum_point(p1, w1, s);
    accum_point(p2, w2, s);
    accum_point(p3, w3, s);
    accum_point(q0, v0, s);
    accum_point(q1, v1, s);
    accum_point(q2, v2, s);
    accum_point(q3, v3, s);

    for (int i = bpos + 1024; i < NP; i += 256) {
        float4 pp = xb[i];
        float  ww = wb[i];
        accum_point(pp, ww, s);
    }

#pragma unroll
    for (int k = 0; k < 45; k++) {
#pragma unroll
        for (int o = 16; o > 0; o >>= 1)
            s[k] += __shfl_xor_sync(0xffffffffu, s[k], o);
    }

    __shared__ float sm[8][45];
    int wid = threadIdx.x >> 5, lane = threadIdx.x & 31;
    if (lane == 0) {
#pragma unroll
        for (int k = 0; k < 45; k++) sm[wid][k] = s[k];
    }
    __syncthreads();
    if (threadIdx.x < 45) {
        float t = 0.f;
#pragma unroll
        for (int q = 0; q < 8; q++) t += sm[q][threadIdx.x];
        g_M[b * 45 + threadIdx.x] = t;
    }
}

// ---------------------------------------------------------------------------
// LAPACK fp32 helpers. slartg is now BRANCHLESS: general path computed
// unconditionally, case outputs selected exactly per the LAPACK branches
// (selected values bit-identical to the branch version in every case).
// ---------------------------------------------------------------------------
#define LEPS    5.9604645e-8f
#define LEPS2   (LEPS * LEPS)
#define LSAFMIN 1.17549435e-38f

__device__ __forceinline__ float slapy2(float x, float y) {
    float xa = fabsf(x), ya = fabsf(y);
    float w = fmaxf(xa, ya), z = fminf(xa, ya);
    if (z == 0.f) return w;
    float t = z / w;
    return w * sqrtf(1.f + t * t);
}

__device__ __forceinline__ void slartg(float f, float g, float& c, float& s, float& r) {
    float d  = sqrtf(f * f + g * g);
    float cg = fabsf(f) / d;
    float rg = copysignf(d, f);
    float sg = g / rg;
    bool g0 = (g == 0.f);
    bool f0 = (f == 0.f);
    float sf0 = (g >= 0.f) ? 1.f : -1.f;
    c = g0 ? 1.f : (f0 ? 0.f       : cg);
    s = g0 ? 0.f : (f0 ? sf0       : sg);
    r = g0 ? f   : (f0 ? fabsf(g)  : rg);
}

__device__ __forceinline__ void slaev2(float a, float b, float c,
                       float& rt1, float& rt2, float& cs1, float& sn1) {
    float sm = a + c, df = a - c, adf = fabsf(df);
    float tb = b + b, ab = fabsf(tb);
    float acmx, acmn;
    if (fabsf(a) > fabsf(c)) { acmx = a; acmn = c; } else { acmx = c; acmn = a; }
    float rt;
    if (adf > ab)      { float t = ab / adf; rt = adf * sqrtf(1.f + t * t); }
    else if (adf < ab) { float t = adf / ab; rt = ab * sqrtf(1.f + t * t); }
    else               { rt = ab * sqrtf(2.f); }
    int sgn1;
    if (sm < 0.f) {
        rt1 = 0.5f * (sm - rt); sgn1 = -1;
        rt2 = (acmx / rt1) * acmn - (b / rt1) * b;
    } else if (sm > 0.f) {
        rt1 = 0.5f * (sm + rt); sgn1 = 1;
        rt2 = (acmx / rt1) * acmn - (b / rt1) * b;
    } else {
        rt1 = 0.5f * rt; rt2 = -0.5f * rt; sgn1 = 1;
    }
    float cs; int sgn2;
    if (df >= 0.f) { cs = df + rt; sgn2 = 1; } else { cs = df - rt; sgn2 = -1; }
    float acs = fabsf(cs);
    if (acs > ab) {
        float ct = -tb / cs;
        sn1 = 1.f / sqrtf(1.f + ct * ct);
        cs1 = ct * sn1;
    } else {
        if (ab == 0.f) { cs1 = 1.f; sn1 = 0.f; }
        else {
            float tn = -cs / tb;
            cs1 = 1.f / sqrtf(1.f + tn * tn);
            sn1 = tn * cs1;
        }
    }
    if (sgn1 == sgn2) { float tn = cs1; cs1 = -sn1; sn1 = tn; }
}

// 9-way predicated select / update (exact moves; no arithmetic)
__device__ __forceinline__ float sel9(const float* a, int k) {
    float r = a[0];
#pragma unroll
    for (int t = 1; t < 9; t++) r = (t == k) ? a[t] : r;
    return r;
}
__device__ __forceinline__ void upd9(float* a, int k, float v) {
#pragma unroll
    for (int t = 0; t < 9; t++) a[t] = (t == k) ? v : a[t];
}

// ---------------------------------------------------------------------------
// Warp-parallel Givens on lane-owned Z columns (round-13/14 passing version).
// ---------------------------------------------------------------------------
__device__ __forceinline__ void rot_cols(float* __restrict__ zc, int lane,
                                         int j, float c, float s) {
    bool isj  = (lane == j);
    bool isj1 = (lane == j + 1);
    int src = lane;
    if (isj)  src = j + 1;
    if (isj1) src = j;
#pragma unroll
    for (int r = 0; r < 9; r++) {
        float partner = __shfl_sync(0xffffffffu, zc[r], src);
        float nv = zc[r];
        if (isj1) nv = c * zc[r] - s * partner;
        if (isj)  nv = s * partner + c * zc[r];
        zc[r] = nv;
    }
}

// ---------------------------------------------------------------------------
// Kernel 2: LAPACK ssyevd replica, register-resident scalar state
// (VERBATIM round-14 passing structure; only slartg's internals changed to
// branchless selects with identical selected values).
// ---------------------------------------------------------------------------
__global__ void __launch_bounds__(32) eig_kernel(float* __restrict__ out) {
    int b = blockIdx.x;
    int lane = threadIdx.x;

    float A[9][9];
#pragma unroll
    for (int i = 0; i < 9; i++)
#pragma unroll
        for (int j = i; j < 9; j++) {
            float v = g_M[b * 45 + tidx(i, j)];
            A[i][j] = v; A[j][i] = v;
        }

    float dd[9], e[9], tau[8];

    // ---- ssytd2 (lower), fully unrolled ----
#pragma unroll
    for (int i = 0; i < 8; i++) {
        float alpha = A[i + 1][i];
        float xn2 = 0.f;
#pragma unroll
        for (int k = i + 2; k < 9; k++) xn2 += A[k][i] * A[k][i];
        float taui;
        if (xn2 == 0.f) {
            taui = 0.f;
            e[i] = alpha;
        } else {
            float xnorm = sqrtf(xn2);
            float beta = -copysignf(slapy2(alpha, xnorm), alpha);
            taui = (beta - alpha) / beta;
            float invd = 1.f / (alpha - beta);
#pragma unroll
            for (int k = i + 2; k < 9; k++) A[k][i] *= invd;
            e[i] = beta;
        }
        if (taui != 0.f) {
            float v[9], wv[9];
            v[i + 1] = 1.f;
#pragma unroll
            for (int k = i + 2; k < 9; k++) v[k] = A[k][i];
#pragma unroll
            for (int r = i + 1; r < 9; r++) {
                float acc = 0.f;
#pragma unroll
                for (int c = i + 1; c < 9; c++) acc += A[r][c] * v[c];
                wv[r] = taui * acc;
            }
            float dxv = 0.f;
#pragma unroll
            for (int r = i + 1; r < 9; r++) dxv += wv[r] * v[r];
            float al2 = -0.5f * taui * dxv;
#pragma unroll
            for (int r = i + 1; r < 9; r++) wv[r] += al2 * v[r];
#pragma unroll
            for (int r = i + 1; r < 9; r++)
#pragma unroll
                for (int c = i + 1; c < 9; c++)
                    A[r][c] -= v[r] * wv[c] + wv[r] * v[c];
        }
        dd[i] = A[i][i];
        tau[i] = taui;
    }
    dd[8] = A[8][8];

    // ---- Z as lane-owned register columns ----
    float zc[9];
#pragma unroll
    for (int r = 0; r < 9; r++) zc[r] = (r == lane) ? 1.f : 0.f;

    // ---- ssteqr (compz='I') ----
    const int NMAXIT = 9 * 30;
    int jtot = 0;
    int l1 = 0;
    while (l1 < 9) {
        if (l1 > 0) upd9(e, l1 - 1, 0.f);
        int m = 8;
        {
            bool found = false;
#pragma unroll
            for (int t = 0; t < 8; t++) {
                if (!found && t >= l1) {
                    float tst = fabsf(e[t]);
                    if (tst == 0.f) { m = t; found = true; }
                    else if (tst <= (sqrtf(fabsf(dd[t])) * sqrtf(fabsf(dd[t + 1]))) * LEPS) {
                        e[t] = 0.f;
                        m = t; found = true;
                    }
                }
            }
        }
        int l = l1, lend = m;
        l1 = m + 1;
        if (lend == l) continue;
        if (fabsf(sel9(dd, lend)) < fabsf(sel9(dd, l))) { int t = l; l = lend; lend = t; }

        if (lend > l) {
            // ---- QL iteration ----
            for (;;) {
                int mm = lend;
                {
                    bool found = false;
#pragma unroll
                    for (int t = 0; t < 8; t++) {
                        if (!found && t >= l && t < lend) {
                            float tst = e[t] * e[t];
                            if (tst <= (LEPS2 * fabsf(dd[t])) * fabsf(dd[t + 1]) + LSAFMIN) {
                                mm = t; found = true;
                                e[t] = 0.f;
                            }
                        }
                    }
                }
                float p = sel9(dd, l);
                if (mm == l) {
                    l++;
                    if (l <= lend) continue;
                    break;
                }
                if (mm == l + 1) {
                    float rt1, rt2, c2, s2;
                    slaev2(sel9(dd, l), sel9(e, l), sel9(dd, l + 1), rt1, rt2, c2, s2);
                    rot_cols(zc, lane, l, c2, s2);
                    upd9(dd, l, rt1); upd9(dd, l + 1, rt2); upd9(e, l, 0.f);
                    l += 2;
                    if (l <= lend) continue;
                    break;
                }
                if (jtot >= NMAXIT) break;
                jtot++;
                float g = (sel9(dd, l + 1) - p) / (2.f * sel9(e, l));
                float r2 = slapy2(g, 1.f);
                g = sel9(dd, mm) - p + sel9(e, l) / (g + copysignf(r2, g));
                float s1 = 1.f, c1 = 1.f;
                p = 0.f;
#pragma unroll
                for (int i = 7; i >= 0; i--) {
                    if (i <= mm - 1 && i >= l) {
                        float f = s1 * e[i];
                        float bb = c1 * e[i];
                        slartg(g, f, c1, s1, r2);
                        if (i != mm - 1) e[i + 1] = r2;
                        g = dd[i + 1] - p;
                        r2 = (dd[i] - g) * s1 + 2.f * c1 * bb;
                        p = s1 * r2;
                        dd[i + 1] = g + p;
                        g = c1 * r2 - bb;
                        rot_cols(zc, lane, i, c1, -s1);
                    }
                }
                upd9(dd, l, sel9(dd, l) - p);
                upd9(e, l, g);
            }
        } else {
            // ---- QR iteration (lend < l) ----
            for (;;) {
                int mm = lend;
                {
                    bool found = false;
#pragma unroll
                    for (int t = 8; t >= 1; t--) {
                        if (!found && t <= l && t > lend) {
                            float tst = e[t - 1] * e[t - 1];
                            if (tst <= (LEPS2 * fabsf(dd[t])) * fabsf(dd[t - 1]) + LSAFMIN) {
                                mm = t; found = true;
                                e[t - 1] = 0.f;
                            }
                        }
                    }
                }
                float p = sel9(dd, l);
                if (mm == l) {
                    l--;
                    if (l >= lend) continue;
                    break;
                }
                if (mm == l - 1) {
                    float rt1, rt2, c2, s2;
                    slaev2(sel9(dd, l - 1), sel9(e, l - 1), sel9(dd, l), rt1, rt2, c2, s2);
                    rot_cols(zc, lane, l - 1, c2, s2);
                    upd9(dd, l - 1, rt1); upd9(dd, l, rt2); upd9(e, l - 1, 0.f);
                    l -= 2;
                    if (l >= lend) continue;
                    break;
                }
                if (jtot >= NMAXIT) break;
                jtot++;
                float g = (sel9(dd, l - 1) - p) / (2.f * sel9(e, l - 1));
                float r2 = slapy2(g, 1.f);
                g = sel9(dd, mm) - p + sel9(e, l - 1) / (g + copysignf(r2, g));
                float s1 = 1.f, c1 = 1.f;
                p = 0.f;
#pragma unroll
                for (int i = 0; i < 8; i++) {
                    if (i >= mm && i <= l - 1) {
                        float f = s1 * e[i];
                        float bb = c1 * e[i];
                        slartg(g, f, c1, s1, r2);
                        if (i > 0 && i != mm) e[i - 1] = r2;
                        g = dd[i] - p;
                        r2 = (dd[i + 1] - g) * s1 + 2.f * c1 * bb;
                        p = s1 * r2;
                        dd[i] = g + p;
                        g = c1 * r2 - bb;
                        rot_cols(zc, lane, i, c1, s1);
                    }
                }
                upd9(dd, l, sel9(dd, l) - p);
                upd9(e, l - 1, g);
            }
        }
    }

    // ---- first strict argmin of dd (== sort's column 0) ----
    int kmin = 0;
    float p0 = dd[0];
#pragma unroll
    for (int j = 1; j < 9; j++)
        if (dd[j] < p0) { p0 = dd[j]; kmin = j; }

    // ---- extract column kmin ----
    float z[9];
#pragma unroll
    for (int r = 0; r < 9; r++) z[r] = __shfl_sync(0xffffffffu, zc[r], kmin);

    // ---- back-transform: z <- H(1)...H(8) z ----
#pragma unroll
    for (int i = 7; i >= 0; i--) {
        if (tau[i] != 0.f) {
            float dot = z[i + 1];
#pragma unroll
            for (int k = i + 2; k < 9; k++) dot += A[k][i] * z[k];
            float tdot = tau[i] * dot;
            z[i + 1] -= tdot;
#pragma unroll
            for (int k = i + 2; k < 9; k++) z[k] -= tdot * A[k][i];
        }
    }

    // ---- normalize ----
    float nrm = 0.f;
#pragma unroll
    for (int k = 0; k < 9; k++) nrm += z[k] * z[k];
    float inv = 1.f / sqrtf(nrm);
    if (lane == 0) {
#pragma unroll
        for (int k = 0; k < 9; k++) out[b * 9 + k] = z[k] * inv;
    }
}

extern "C" void kernel_launch(void* const* d_in, const int* in_sizes, int n_in,
                              void* d_out, int out_size) {
    const float4* x = (const float4*)d_in[0];  // x_in  (256,1,20000,4) f32
    const float*  w = (const float*)d_in[1];   // weights (256,20000)   f32
    float* out = (float*)d_out;                // (256,9) f32

    xtx_kernel<<<NB, 256>>>(x, w);
    eig_kernel<<<NB, 32>>>(out);
}